// round 16
// baseline (speedup 1.0000x reference)
#include <cuda_runtime.h>

#define NSTATES 128
#define MAXB    256
#define HOFF    80          // float offset of second p-half (16-float pad)

// Inter-kernel scratch (allocation-free: __device__ globals).
__device__ float g_u[MAXB * NSTATES];    // forward:  u = T^T alpha_mid
__device__ float g_d[MAXB * NSTATES];    // backward: delta_{mid+1}
__device__ float g_Cf[MAXB];
__device__ float g_Cb[MAXB];

#define FMA2(acc, p, t) \
    asm volatile("fma.rn.f32x2 %0, %1, %2, %0;" : "+l"(acc) : "l"(p), "l"(t))
#define ADD2(acc, b) \
    asm volatile("add.rn.f32x2 %0, %0, %1;" : "+l"(acc) : "l"(b))

static __device__ __forceinline__ float warp_max(float v) {
#pragma unroll
    for (int d = 16; d; d >>= 1) v = fmaxf(v, __shfl_xor_sync(0xffffffffu, v, d));
    return v;
}
static __device__ __forceinline__ float warp_sum(float v) {
#pragma unroll
    for (int d = 16; d; d >>= 1) v += __shfl_xor_sync(0xffffffffu, v, d);
    return v;
}

// One scan step, dual-output / split-K layout:
// thread (u, h) accumulates partials for outputs j=u and j=u+64 over the
// K-half i in [64h, 64h+64). Partner (u, h^1) sits in the adjacent lane;
// halves combine via shfl_xor(.,1). Thread then owns j_out = u + 64h.
// Delivered SMEM bytes halve vs the 1-output layout (256B/thread/step).
// MODE 0: plain. MODE 1: also block-max of p' into wred. MODE 2: apply renorm.
template <int MODE>
static __device__ __forceinline__ float crf_step(
    const unsigned long long (&tc0)[32], const unsigned long long (&tc1)[32],
    const float* __restrict__ pin, float* __restrict__ pout,
    float obsv, float& C, float* wred,
    int warp, int lane, int slot, int h)
{
    float eo = __expf(obsv);

    unsigned long long a00 = 0ull, a01 = 0ull, a10 = 0ull, a11 = 0ull;
    const ulonglong2* pv = reinterpret_cast<const ulonglong2*>(pin + h * HOFF);
#pragma unroll
    for (int k = 0; k < 16; ++k) {
        ulonglong2 pa = pv[k];            // p[64h+4k .. 64h+4k+3]
        FMA2(a00, pa.x, tc0[2 * k + 0]);
        FMA2(a01, pa.y, tc0[2 * k + 1]);
        FMA2(a10, pa.x, tc1[2 * k + 0]);
        FMA2(a11, pa.y, tc1[2 * k + 1]);
    }
    ADD2(a00, a01);
    ADD2(a10, a11);
    float x0, y0, x1, y1;
    asm("mov.b64 {%0, %1}, %2;" : "=f"(x0), "=f"(y0) : "l"(a00));
    asm("mov.b64 {%0, %1}, %2;" : "=f"(x1), "=f"(y1) : "l"(a10));
    float q0 = x0 + y0;                   // partial q[u]      (this K-half)
    float q1 = x1 + y1;                   // partial q[u+64]   (this K-half)

    // Combine K-halves with the adjacent lane; both lanes end with full sums.
    q0 += __shfl_xor_sync(0xffffffffu, q0, 1);
    q1 += __shfl_xor_sync(0xffffffffu, q1, 1);
    float q = h ? q1 : q0;                // this thread's output state

    if (MODE == 2) {
        float4 w = *reinterpret_cast<const float4*>(wred);
        float mx = fmaxf(fmaxf(w.x, w.y), fmaxf(w.z, w.w));
        q = q * __fdividef(1.0f, mx);
        C += __logf(mx);
    }

    float pn = q * eo;
    pout[slot] = pn;

    if (MODE == 1) {
        float m = warp_max(pn);
        if (lane == 0) wred[warp] = m;
    }
    __syncthreads();
    return pn;
}

// Half-scan kernel: CTA 2b = forward half of batch b, CTA 2b+1 = backward half.
__global__ void __launch_bounds__(128, 1)
crf_half_kernel(const float* __restrict__ obs,
                const float* __restrict__ logA,
                int T)
{
    const int cta  = blockIdx.x;
    const int b    = cta >> 1;
    const int dir  = cta & 1;            // 0 = forward, 1 = backward
    const int tau  = threadIdx.x;
    const int u    = tau >> 1;           // output pair index [0,64)
    const int h    = tau & 1;            // K-half
    const int jout = u + 64 * h;         // final owned state
    const int slot = u + HOFF * h;       // padded SMEM slot for jout
    const int warp = tau >> 5;
    const int lane = tau & 31;

    __shared__ __align__(16) float psh[2][2 * HOFF];   // [pingpong][padded states]
    __shared__ __align__(16) float wred[4];

    // Register tiles: for outputs u and u+64, K-half [64h, 64h+64).
    // fwd: columns of T = exp(logA); bwd: rows of T.
    unsigned long long tc0[32], tc1[32];
#pragma unroll
    for (int m = 0; m < 32; ++m) {
        const int i0 = 64 * h + 2 * m;
        float2 t2, s2;
        if (dir == 0) {
            t2.x = expf(logA[(i0 + 0) * NSTATES + u]);
            t2.y = expf(logA[(i0 + 1) * NSTATES + u]);
            s2.x = expf(logA[(i0 + 0) * NSTATES + u + 64]);
            s2.y = expf(logA[(i0 + 1) * NSTATES + u + 64]);
        } else {
            t2.x = expf(logA[u * NSTATES + i0 + 0]);
            t2.y = expf(logA[u * NSTATES + i0 + 1]);
            s2.x = expf(logA[(u + 64) * NSTATES + i0 + 0]);
            s2.y = expf(logA[(u + 64) * NSTATES + i0 + 1]);
        }
        tc0[m] = *reinterpret_cast<unsigned long long*>(&t2);
        tc1[m] = *reinterpret_cast<unsigned long long*>(&s2);
    }

    const int mid    = T >> 1;
    const int row0   = dir ? (T - 1) : 0;
    const int nsteps = dir ? (T - 2 - mid) : mid;
    const int dS     = dir ? -NSTATES : NSTATES;
    const int hi     = (T - 1) * NSTATES;

    const float* obj = obs + (size_t)b * ((size_t)T * NSTATES) + jout;

    // ---- init: p = exp(obs[row0] - m0), C = m0 ----
    float o0 = obj[row0 * NSTATES];
    float m0 = warp_max(o0);
    if (lane == 0) wred[warp] = m0;
    __syncthreads();
    m0 = fmaxf(fmaxf(wred[0], wred[1]), fmaxf(wred[2], wred[3]));
    float C = m0;
    psh[0][slot] = __expf(o0 - m0);
    __syncthreads();

    // ---- prefetch ring: next 4 obs rows in scan order ----
    float f0 = obj[row0 * NSTATES + 1 * dS];
    float f1 = obj[row0 * NSTATES + 2 * dS];
    float f2 = obj[row0 * NSTATES + 3 * dS];
    float f3 = obj[row0 * NSTATES + 4 * dS];
    int off = row0 * NSTATES + 5 * dS;

    const int G   = nsteps >> 3;   // groups of 8 steps (renorm once per group)
    const int rem = nsteps & 7;
    float pn = psh[0][slot];

#define PF(fr) do { int oc = off; oc = (oc < 0) ? 0 : oc; oc = (oc > hi) ? hi : oc; \
                    fr = __ldg(obj + oc); off += dS; } while (0)
#define ST(MODE, IN, OUT, o) \
    pn = crf_step<MODE>(tc0, tc1, psh[IN], psh[OUT], o, C, wred, warp, lane, slot, h)

    for (int g = 0; g < G; ++g) {
        float o;
        o = f0; PF(f0); ST(0, 0, 1, o);
        o = f1; PF(f1); ST(0, 1, 0, o);
        o = f2; PF(f2); ST(0, 0, 1, o);
        o = f3; PF(f3); ST(0, 1, 0, o);
        o = f0; PF(f0); ST(0, 0, 1, o);
        o = f1; PF(f1); ST(0, 1, 0, o);
        o = f2; PF(f2); ST(1, 0, 1, o);
        o = f3; PF(f3); ST(2, 1, 0, o);
    }

    // ---- tail (rem <= 7 plain steps; drift bounded, fp32-safe) ----
    {
        float o;
        if (rem > 0) { o = f0; PF(f0); ST(0, 0, 1, o); }
        if (rem > 1) { o = f1; PF(f1); ST(0, 1, 0, o); }
        if (rem > 2) { o = f2; PF(f2); ST(0, 0, 1, o); }
        if (rem > 3) { o = f3;         ST(0, 1, 0, o); }
        if (rem > 4) { o = f0;         ST(0, 0, 1, o); }
        if (rem > 5) { o = f1;         ST(0, 1, 0, o); }
        if (rem > 6) { o = f2;         ST(0, 0, 1, o); }
    }
#undef PF
#undef ST

    if (dir == 0) {
        // One extra plain matvec (eo = 1): u = T^T alpha_mid.
        if (nsteps & 1)
            pn = crf_step<0>(tc0, tc1, psh[1], psh[0], 0.0f, C, wred, warp, lane, slot, h);
        else
            pn = crf_step<0>(tc0, tc1, psh[0], psh[1], 0.0f, C, wred, warp, lane, slot, h);
        g_u[b * NSTATES + jout] = pn;
        if (tau == 0) g_Cf[b] = C;
    } else {
        g_d[b * NSTATES + jout] = pn;
        if (tau == 0) g_Cb[b] = C;
    }
}

// Combine: out[b] = -(Cf + Cb + log(sum_j u[j] * delta[j]))
__global__ void __launch_bounds__(128, 1)
crf_combine_kernel(float* __restrict__ out)
{
    const int b    = blockIdx.x;
    const int j    = threadIdx.x;
    const int warp = j >> 5;
    const int lane = j & 31;
    __shared__ float wred[4];

    float v = g_u[b * NSTATES + j] * g_d[b * NSTATES + j];
    float s = warp_sum(v);
    if (lane == 0) wred[warp] = s;
    __syncthreads();
    if (j == 0) {
        float tot = (wred[0] + wred[1]) + (wred[2] + wred[3]);
        out[b] = -(g_Cf[b] + g_Cb[b] + logf(tot));
    }
}

extern "C" void kernel_launch(void* const* d_in, const int* in_sizes, int n_in,
                              void* d_out, int out_size)
{
    const float* obs  = (const float*)d_in[0];   // [B, T, S] fp32
    const float* logA = (const float*)d_in[1];   // [S, S] fp32
    float* out = (float*)d_out;                  // [B] fp32

    const int B = out_size;                      // 64
    const int T = in_sizes[0] / (B * NSTATES);   // 4096

    crf_half_kernel<<<2 * B, NSTATES>>>(obs, logA, T);
    crf_combine_kernel<<<B, NSTATES>>>(out);
}